// round 9
// baseline (speedup 1.0000x reference)
#include <cuda_runtime.h>

#define BATCH   64
#define TSTEPS  1024
#define DIM     512
#define NCTA    128          // 8 b-groups x 16 j-groups; co-resident on 148 SMs
#define NBG     8            // b-groups
#define NJG     16           // j-groups per b-group

#define HSTRIDE 576          // staged row stride: 16 chunks x (32 data + 4 pad)
#define PROW    33           // part row stride (floats)
#define PSEG    (8 * PROW)   // part segment stride (264 floats)

// ---------------- scratch (device globals; no allocations) ------------------
__device__ float    g_h[2][BATCH * DIM];          // ping-pong hidden state
__device__ unsigned g_flag[TSTEPS * NBG * NJG];   // h_t tile-ready flags

// ---------------- f32x2 packed-FMA helpers (sm_100+ PTX) --------------------
static __device__ __forceinline__ unsigned long long packf2(float lo, float hi) {
    unsigned long long r;
    asm("mov.b64 %0, {%1, %2};" : "=l"(r) : "f"(lo), "f"(hi));
    return r;
}
static __device__ __forceinline__ void unpackf2(unsigned long long v, float& lo, float& hi) {
    asm("mov.b64 {%0, %1}, %2;" : "=f"(lo), "=f"(hi) : "l"(v));
}
static __device__ __forceinline__ unsigned long long fma2(
    unsigned long long a, unsigned long long b, unsigned long long c) {
    unsigned long long d;
    asm("fma.rn.f32x2 %0, %1, %2, %3;" : "=l"(d) : "l"(a), "l"(b), "l"(c));
    return d;
}

// ---------------------------------------------------------------------------
// Matmul partials: thread = (warp w: k-slice 64) x (cg: col pair) x (ks: k half)
// 8 rows x 2 cols over 32 k. Reads ONLY chunks 2w,2w+1 of the staged tile
// (the chunks warp w itself staged) -> no CTA barrier between stage and mm.
// Per warp: 64 LDS.128 (conflict-free, 144B chunk spacing) + 256 fma2.
// ---------------------------------------------------------------------------
static __device__ __forceinline__ void mm_partials(
    const float* __restrict__ sm, const unsigned long long w2[2][16],
    int smoff, int seg, int cg, float* __restrict__ part)
{
    unsigned long long acc[8][2];
#pragma unroll
    for (int r = 0; r < 8; r++) { acc[r][0] = 0ULL; acc[r][1] = 0ULL; }

#pragma unroll
    for (int m = 0; m < 8; m++) {
#pragma unroll
        for (int r = 0; r < 8; r++) {
            ulonglong2 h2 = *(const ulonglong2*)(sm + r * HSTRIDE + smoff + m * 4);
            acc[r][0] = fma2(h2.x, w2[0][2 * m + 0], acc[r][0]);
            acc[r][0] = fma2(h2.y, w2[0][2 * m + 1], acc[r][0]);
            acc[r][1] = fma2(h2.x, w2[1][2 * m + 0], acc[r][1]);
            acc[r][1] = fma2(h2.y, w2[1][2 * m + 1], acc[r][1]);
        }
    }
#pragma unroll
    for (int r = 0; r < 8; r++) {
#pragma unroll
        for (int c = 0; c < 2; c++) {
            float lo, hi;
            unpackf2(acc[r][c], lo, hi);
            part[seg * PSEG + r * PROW + cg * 2 + c] = lo + hi;
        }
    }
}

// ---------------------------------------------------------------------------
// Fused persistent kernel: h_{t+1} = tanh( (x_t@W + b) + h_t@Wr )
// CTA c: rows [b0,b0+8), cols [j0,j0+32). 2 CTA barriers per step:
//   S2 (part_r/part_x complete before reduce), S4 (reduce reads done before
//   part overwrite + h-tile stores done before single st.release flag).
// Each warp stages & consumes only its own 2 chunks of hs/xs (syncwarp only).
// mm_x (gemm for t+1, separate part_x buffer) hides the h store->load RTT.
// ---------------------------------------------------------------------------
__global__ void __launch_bounds__(256, 1) rnn_fused_kernel(
    const float* __restrict__ W,      // [512,512] row-major
    const float* __restrict__ Wr,     // [512,512] row-major
    const float* __restrict__ x,      // [64,1024,512]
    const float* __restrict__ bias,   // [512]
    float* __restrict__ out)          // [64,512]
{
    __shared__ float hs[8 * HSTRIDE];        // staged h tile   18 KB
    __shared__ float xs[8 * HSTRIDE];        // staged x tile   18 KB
    __shared__ float part_r[16 * PSEG];      // recurrence partials 16.9 KB
    __shared__ float part_x[16 * PSEG];      // gemm partials       16.9 KB

    const int tid  = threadIdx.x;
    const int w    = tid >> 5;               // warp: k-slice [w*64, +64)
    const int lane = tid & 31;
    const int cg   = lane >> 1;              // col pair: cols j0 + cg*2 + {0,1}
    const int ks   = lane & 1;               // k half within slice
    const int c    = blockIdx.x;
    const int bg   = c >> 4;
    const int jg   = c & 15;
    const int b0   = bg * 8;
    const int j0   = jg * 32;

    const int kb    = w * 64 + ks * 32;      // logical k base
    const int smoff = w * 72 + ks * 36;      // padded smem base (chunk 2w+ks)
    const int seg   = w * 2 + ks;

    // persistent packed weights: (k, k+1) pairs for this thread's 2 columns
    unsigned long long wr2[2][16], wx2[2][16];
#pragma unroll
    for (int cc = 0; cc < 2; cc++) {
        const int j = j0 + cg * 2 + cc;
#pragma unroll
        for (int p = 0; p < 16; p++) {
            const int k = kb + 2 * p;
            wr2[cc][p] = packf2(Wr[(size_t)k * DIM + j], Wr[(size_t)(k + 1) * DIM + j]);
            wx2[cc][p] = packf2(W[(size_t)k * DIM + j],  W[(size_t)(k + 1) * DIM + j]);
        }
    }
    const int   rrow = tid >> 5;             // reduce/output row (== w)
    const int   rcol = tid & 31;             // reduce/output col
    const float bv   = bias[j0 + rcol];

    // warp-chunk staging map: float4 index v in a chunk -> (row, col4)
    const int sr0 = lane >> 3,        sc0 = lane & 7;         // v = lane
    const int sr1 = (lane + 32) >> 3, sc1 = (lane + 32) & 7;  // v = lane+32

    // ---- prologue ----
    // stage x[0] into xs (own chunks) and run gemm -> part_x (xw for t=0)
    float4 xt[4];
#pragma unroll
    for (int pc = 0; pc < 2; pc++) {
        const int p = w * 2 + pc;
        const float* xb = x + ((size_t)b0 * TSTEPS + 0) * DIM;   // row-offset below
        float4 d0 = __ldg((const float4*)(x + ((size_t)(b0 + sr0) * TSTEPS + 0) * DIM + p * 32) + sc0);
        float4 d1 = __ldg((const float4*)(x + ((size_t)(b0 + sr1) * TSTEPS + 0) * DIM + p * 32) + sc1);
        (void)xb;
        *(float4*)&xs[sr0 * HSTRIDE + p * 36 + sc0 * 4] = d0;
        *(float4*)&xs[sr1 * HSTRIDE + p * 36 + sc1 * 4] = d1;
        // zero hs own chunks (h_0 = 0; never read from gmem)
        const float4 z = make_float4(0.f, 0.f, 0.f, 0.f);
        *(float4*)&hs[sr0 * HSTRIDE + p * 36 + sc0 * 4] = z;
        *(float4*)&hs[sr1 * HSTRIDE + p * 36 + sc1 * 4] = z;
    }
    __syncwarp();
    mm_partials(xs, wx2, smoff, seg, cg, part_x);
    // prefetch x[1] into regs (consumed at iter 0 step 5)
#pragma unroll
    for (int pc = 0; pc < 2; pc++) {
        const int p = w * 2 + pc;
        xt[pc * 2 + 0] = __ldg((const float4*)(x + ((size_t)(b0 + sr0) * TSTEPS + 1) * DIM + p * 32) + sc0);
        xt[pc * 2 + 1] = __ldg((const float4*)(x + ((size_t)(b0 + sr1) * TSTEPS + 1) * DIM + p * 32) + sc1);
    }
    __syncwarp();

    for (int t = 0; t < TSTEPS; t++) {
        // ---- 1: recurrence mm on own chunks of hs ----
        mm_partials(hs, wr2, smoff, seg, cg, part_r);
        __syncthreads();                     // S2: all part_r & part_x written

        // ---- 3: reduce (xw + recurrence), tanh, store h row ----
        float s = bv;
#pragma unroll
        for (int s8 = 0; s8 < 16; s8++) s += part_x[s8 * PSEG + rrow * PROW + rcol];
#pragma unroll
        for (int s8 = 0; s8 < 16; s8++) s += part_r[s8 * PSEG + rrow * PROW + rcol];
        float hv = tanhf(s);
        if (t == TSTEPS - 1) {
            out[(b0 + rrow) * DIM + j0 + rcol] = hv;
            return;
        }
        __stcg(&g_h[(t + 1) & 1][(b0 + rrow) * DIM + j0 + rcol], hv);
        __syncthreads();                     // S4: part reads done, all h stores done

        // ---- publish one flag for this CTA's h tile (ordered after S4) ----
        if (tid == 0) {
            unsigned* f = &g_flag[((unsigned)(t + 1) * NBG + bg) * NJG + jg];
            asm volatile("st.release.gpu.global.u32 [%0], %1;"
                         :: "l"(f), "r"(1u) : "memory");
        }

        // ---- 5: stage xs (own chunks) + issue x[t+2] prefetch, then mm_x ----
#pragma unroll
        for (int pc = 0; pc < 2; pc++) {
            const int p = w * 2 + pc;
            *(float4*)&xs[sr0 * HSTRIDE + p * 36 + sc0 * 4] = xt[pc * 2 + 0];
            *(float4*)&xs[sr1 * HSTRIDE + p * 36 + sc1 * 4] = xt[pc * 2 + 1];
        }
        __syncwarp();
        {
            const int tn = (t + 2 < TSTEPS) ? (t + 2) : (TSTEPS - 1);
#pragma unroll
            for (int pc = 0; pc < 2; pc++) {
                const int p = w * 2 + pc;
                xt[pc * 2 + 0] = __ldg((const float4*)(
                    x + ((size_t)(b0 + sr0) * TSTEPS + tn) * DIM + p * 32) + sc0);
                xt[pc * 2 + 1] = __ldg((const float4*)(
                    x + ((size_t)(b0 + sr1) * TSTEPS + tn) * DIM + p * 32) + sc1);
            }
        }
        mm_partials(xs, wx2, smoff, seg, cg, part_x);   // xw for t+1

        // ---- 7: poll own chunks of h_{t+1}, stage into hs (no CTA barrier) --
        {
            const float* hbuf = g_h[(t + 1) & 1];
#pragma unroll
            for (int pc = 0; pc < 2; pc++) {
                const int p = w * 2 + pc;               // producer j-group
                const unsigned* f = &g_flag[((unsigned)(t + 1) * NBG + bg) * NJG + p];
                unsigned v;
                do {
                    asm volatile("ld.acquire.gpu.global.u32 %0, [%1];"
                                 : "=r"(v) : "l"(f) : "memory");
                } while (v == 0u);
                float4 d0 = __ldcg((const float4*)(hbuf + (b0 + sr0) * DIM + p * 32) + sc0);
                float4 d1 = __ldcg((const float4*)(hbuf + (b0 + sr1) * DIM + p * 32) + sc1);
                *(float4*)&hs[sr0 * HSTRIDE + p * 36 + sc0 * 4] = d0;
                *(float4*)&hs[sr1 * HSTRIDE + p * 36 + sc1 * 4] = d1;
            }
        }
        __syncwarp();
    }
}

// ============================================================================
extern "C" void kernel_launch(void* const* d_in, const int* in_sizes, int n_in,
                              void* d_out, int out_size)
{
    const float* x    = (const float*)d_in[0];   // [64,1024,512]
    const float* W    = (const float*)d_in[1];   // [512,512]
    const float* Wr   = (const float*)d_in[2];   // [512,512]
    const float* bias = (const float*)d_in[3];   // [512]
    float* out = (float*)d_out;                  // [64,512]

    void* flag_p; cudaGetSymbolAddress(&flag_p, g_flag);

    // per-launch reset (graph-capturable, replay-safe)
    cudaMemsetAsync(flag_p, 0, sizeof(unsigned) * TSTEPS * NBG * NJG);

    rnn_fused_kernel<<<NCTA, 256>>>(W, Wr, x, bias, out);
}